// round 5
// baseline (speedup 1.0000x reference)
#include <cuda_runtime.h>

// Four-step 1024-point inverse FFT (reference == normalized inverse DFT).
//   1024 = 32 x 32, one warp lane per column, one warp per row.
//   A[k1,b]    = FFT32_a( x[32a+b] )         (register FFT, thread = b = lane)
//   A'[k1,b]   = A[k1,b] * (1/1024) * W1024^{b*k1}   (precomputed table)
//   X[k1+32k2] = FFT32_b( A'[k1,b] )         (after XOR-swizzled smem transpose)
// v5 vs v4: twiddle factors come from an 8KB L1-resident __device__ table
// (kills ~250 fma inst/thread of on-the-fly generation); the transpose is a
// single float2 buffer with XOR bank swizzle (32 STS.64 + 32 LDS.64 instead of
// 128 32-bit ops). The kernel is issue-count-bound, so every removed
// instruction converts directly into DRAM utilization.

#define NFFT 1024
#define WARPS_PER_CTA 4
#define NT (32 * WARPS_PER_CTA)

// (1/1024) * W1024^{k1*b}, index = k1*32 + b.  Filled by init_twiddles once
// per launch (idempotent, graph-capturable).
__device__ float2 g_tw[1024];

__global__ void init_twiddles()
{
    const int i = blockIdx.x * blockDim.x + threadIdx.x;   // 0..1023
    const int k1 = i >> 5, b = i & 31;
    const int m = (k1 * b) & 1023;          // exact; reduces __sincosf argument
    float sn, cs;
    __sincosf(6.135923151542565e-3f * (float)m, &sn, &cs);  // 2*pi/1024 * m
    g_tw[i] = make_float2(cs * (1.0f / 1024.0f), sn * (1.0f / 1024.0f));
}

__device__ __forceinline__ int brev5(int x) {
    return ((x & 1) << 4) | ((x & 2) << 2) | (x & 4) | ((x & 8) >> 2) | ((x & 16) >> 4);
}

// In-place radix-2 DIF FFT-32, inverse sign (W = e^{+2*pi*i/32}).
// Input natural order; output bit-reversed: x[p] holds X[brev5(p)].
// Fully unrolled: all twiddles become literal constants (trivial ones fold).
__device__ __forceinline__ void fft32_dif(float* xr, float* xi) {
    const float TC[16] = {
        1.0f,           0.98078528040f,  0.92387953251f,  0.83146961230f,
        0.70710678119f, 0.55557023302f,  0.38268343236f,  0.19509032202f,
        0.0f,          -0.19509032202f, -0.38268343236f, -0.55557023302f,
       -0.70710678119f,-0.83146961230f, -0.92387953251f, -0.98078528040f };
    const float TS[16] = {
        0.0f,           0.19509032202f,  0.38268343236f,  0.55557023302f,
        0.70710678119f, 0.83146961230f,  0.92387953251f,  0.98078528040f,
        1.0f,           0.98078528040f,  0.92387953251f,  0.83146961230f,
        0.70710678119f, 0.55557023302f,  0.38268343236f,  0.19509032202f };

    #pragma unroll
    for (int s = 0; s < 5; s++) {
        const int L = 32 >> s;
        const int half = L >> 1;
        #pragma unroll
        for (int s0 = 0; s0 < 32; s0 += L) {
            #pragma unroll
            for (int j = 0; j < half; j++) {
                const int i0 = s0 + j;
                const int i1 = i0 + half;
                const int tw = j << s;              // < 16
                const float ur = xr[i0], ui = xi[i0];
                const float vr = xr[i1], vi = xi[i1];
                const float dr = ur - vr, di = ui - vi;
                xr[i0] = ur + vr;
                xi[i0] = ui + vi;
                xr[i1] = dr * TC[tw] - di * TS[tw];
                xi[i1] = dr * TS[tw] + di * TC[tw];
            }
        }
    }
}

__global__ void __launch_bounds__(NT, 6)
ifft1024_v5(const float* __restrict__ re,
            const float* __restrict__ im,
            float* __restrict__ im_unused_alias,   // keep signature simple
            float* __restrict__ out,
            int batch);

__global__ void __launch_bounds__(NT, 6)
ifft1024_v5_kernel(const float* __restrict__ re,
                   const float* __restrict__ im,
                   float* __restrict__ out,
                   int batch)
{
    // One float2 32x32 transpose buffer per warp. XOR swizzle (col = b ^ k1)
    // makes both directions conflict-free with no padding.
    __shared__ float2 tbuf[WARPS_PER_CTA][1024];

    const int lane = threadIdx.x & 31;
    const int w    = threadIdx.x >> 5;
    const size_t row = (size_t)blockIdx.x * WARPS_PER_CTA + w;

    const float* __restrict__ rr = re + row * NFFT;
    const float* __restrict__ ri = im + row * NFFT;

    // Load x[32a + lane] (each warp instruction = one coalesced 128B segment).
    float xr[32], xi[32];
    #pragma unroll
    for (int a = 0; a < 32; a++) {
        xr[a] = rr[32 * a + lane];
        xi[a] = ri[32 * a + lane];
    }

    // FFT over a.  xr[p] = A[brev5(p), lane].
    fft32_dif(xr, xi);

    // Twiddle (scale folded in): A'[k1, b] = A[k1, b] * g_tw[k1*32 + b].
    // Table reads are L1-resident after first touch; addresses depend only on
    // lane, so loads can be hoisted over the apply chain by the scheduler.
    #pragma unroll
    for (int p = 0; p < 32; p++) {
        const int k1 = brev5(p);
        const float2 t = __ldg(&g_tw[(k1 << 5) + lane]);
        const float ar = xr[p], ai = xi[p];
        xr[p] = ar * t.x - ai * t.y;
        xi[p] = ar * t.y + ai * t.x;
    }

    // XOR-swizzled float2 transpose.
    // Write A'[k1, lane] at sb[k1*32 + (lane ^ k1)]  -> banks distinct per phase.
    float2* sb = tbuf[w];
    #pragma unroll
    for (int p = 0; p < 32; p++) {
        const int k1 = brev5(p);
        sb[(k1 << 5) + (lane ^ k1)] = make_float2(xr[p], xi[p]);
    }
    __syncwarp();
    // Read row k1 = lane: A'[lane, b] at sb[lane*32 + (b ^ lane)].
    #pragma unroll
    for (int b = 0; b < 32; b++) {
        const float2 t = sb[(lane << 5) + (b ^ lane)];
        xr[b] = t.x;
        xi[b] = t.y;
    }

    // FFT over b.  xr[p] = X[lane + 32*brev5(p)]  (already scaled).
    fft32_dif(xr, xi);

    // Coalesced stores (128B per warp instruction).
    float* __restrict__ outr = out + row * NFFT;
    float* __restrict__ outi = out + (size_t)batch * NFFT + row * NFFT;
    #pragma unroll
    for (int p = 0; p < 32; p++) {
        const int k2 = brev5(p);
        outr[lane + 32 * k2] = xr[p];
        outi[lane + 32 * k2] = xi[p];
    }
}

extern "C" void kernel_launch(void* const* d_in, const int* in_sizes, int n_in,
                              void* d_out, int out_size)
{
    // metadata order: re, im, wr_u, wr_l, wi_u, wi_l (matrices unused: the
    // u/l split sums exactly to the IDFT matrix; the reference pipeline is a
    // normalized 1024-point inverse DFT, computed here directly).
    const float* re = (const float*)d_in[0];
    const float* im = (const float*)d_in[1];
    float* out = (float*)d_out;

    const int batch = in_sizes[0] / NFFT;            // 32768

    init_twiddles<<<8, 128>>>();
    ifft1024_v5_kernel<<<batch / WARPS_PER_CTA, NT>>>(re, im, out, batch);
}